// round 2
// baseline (speedup 1.0000x reference)
#include <cuda_runtime.h>
#include <cuda_bf16.h>

// Ball query: for each of NQ=32768 query points (p_grid), find first K=10
// points of x (NP=8192) with d2 <= RADIUS^2, in ascending index order
// (matches reference top_k(-score) trick exactly).
//
// Output buffer (float32), out_size = NQ*K + NQ*K*3:
//   [0 .. NQ*K)            mapping  (index as float, 0 if not found)
//   [NQ*K .. NQ*K*4)       gathered coords (x[mapping] or 0 if not found)

#define NP 8192
#define NQ 32768
#define KNN 10
#define R2 0.0625f
#define MAP_ELEMS (NQ * KNN)

__global__ void __launch_bounds__(256, 2)
bq_kernel(const float* __restrict__ x,
          const float* __restrict__ pg,
          float* __restrict__ out)
{
    // SoA shared copy of x: conflict-free LDS.32
    extern __shared__ float smem[];
    float* xs = smem;
    float* ys = smem + NP;
    float* zs = smem + 2 * NP;

    for (int i = threadIdx.x; i < NP; i += blockDim.x) {
        float3 p = *reinterpret_cast<const float3*>(x + 3 * i);
        xs[i] = p.x;
        ys[i] = p.y;
        zs[i] = p.z;
    }
    __syncthreads();

    const int lane   = threadIdx.x & 31;
    const int gwarp  = (blockIdx.x * blockDim.x + threadIdx.x) >> 5;
    const int nwarps = (gridDim.x * blockDim.x) >> 5;
    const unsigned lt_mask = (1u << lane) - 1u;

    for (int q = gwarp; q < NQ; q += nwarps) {
        const float qx = pg[3 * q + 0];
        const float qy = pg[3 * q + 1];
        const float qz = pg[3 * q + 2];
        // reference: d2 = |q|^2 + |p|^2 - 2*dot  (expanded form)
        const float q2 = qx * qx + qy * qy + qz * qz;

        int cnt = 0;
        for (int base = 0; base < NP; base += 32) {
            const int i = base + lane;
            const float px = xs[i];
            const float py = ys[i];
            const float pz = zs[i];
            const float ps  = px * px + py * py + pz * pz;
            const float dot = qx * px + qy * py + qz * pz;
            const float d2  = q2 + ps - 2.0f * dot;
            const bool valid = (d2 <= R2);
            const unsigned mask = __ballot_sync(0xffffffffu, valid);
            if (valid) {
                const int slot = cnt + __popc(mask & lt_mask);
                if (slot < KNN) {
                    out[(size_t)q * KNN + slot] = (float)i;
                    float* oc = out + MAP_ELEMS + ((size_t)q * KNN + slot) * 3;
                    oc[0] = px;
                    oc[1] = py;
                    oc[2] = pz;
                }
            }
            cnt += __popc(mask);      // warp-uniform
            if (cnt >= KNN) break;    // warp-uniform early exit
        }

        // zero-fill unfound slots (mapping=0, coords=0)
        const int c = cnt < KNN ? cnt : KNN;
        if (lane >= c && lane < KNN) {
            out[(size_t)q * KNN + lane] = 0.0f;
            float* oc = out + MAP_ELEMS + ((size_t)q * KNN + lane) * 3;
            oc[0] = 0.0f;
            oc[1] = 0.0f;
            oc[2] = 0.0f;
        }
    }
}

extern "C" void kernel_launch(void* const* d_in, const int* in_sizes, int n_in,
                              void* d_out, int out_size)
{
    const float* x  = (const float*)d_in[0];   // (1, 8192, 3)
    const float* pg = (const float*)d_in[1];   // (1, 64, 32, 16, 3) -> (32768, 3)
    // defensive: swap if metadata order differs
    if (n_in >= 2 && in_sizes[0] == NQ * 3 && in_sizes[1] == NP * 3) {
        const float* t = x; x = pg; pg = t;
    }
    float* out = (float*)d_out;

    const int threads = 256;
    const int blocks  = 304;                    // ~2 CTAs/SM on 148-152 SMs
    const size_t smem = 3 * NP * sizeof(float); // 96 KB

    static bool attr_set = false;
    if (!attr_set) {
        cudaFuncSetAttribute(bq_kernel,
                             cudaFuncAttributeMaxDynamicSharedMemorySize,
                             (int)smem);
        attr_set = true;
    }

    bq_kernel<<<blocks, threads, smem>>>(x, pg, out);
}

// round 3
// speedup vs baseline: 1.1778x; 1.1778x over previous
#include <cuda_runtime.h>
#include <cuda_bf16.h>

// Ball query: for each of NQ=32768 query points (p_grid), find first K=10
// points of x (NP=8192) with d2 <= RADIUS^2, ascending index order.
//
// Output buffer (float32), out_size = NQ*K + NQ*K*3:
//   [0 .. NQ*K)        mapping (index as float, 0 if not found)
//   [NQ*K .. NQ*K*4)   gathered coords (x[mapping], zeroed if not found)
//
// R2 design: only the first NPC points live in SMEM (warps early-exit after
// ~200-500 points; P(scan past 2048) ~ 2-3%). 24KB smem -> ~6-8 CTAs/SM.

#define NP 8192
#define NQ 32768
#define KNN 10
#define R2C 0.0625f
#define MAP_ELEMS (NQ * KNN)
#define NPC 2048   // points cached in SMEM

__global__ void __launch_bounds__(256)
bq_kernel(const float* __restrict__ x,
          const float* __restrict__ pg,
          float* __restrict__ out)
{
    __shared__ float xs[NPC];
    __shared__ float ys[NPC];
    __shared__ float zs[NPC];

    for (int i = threadIdx.x; i < NPC; i += blockDim.x) {
        float3 p = *reinterpret_cast<const float3*>(x + 3 * i);
        xs[i] = p.x;
        ys[i] = p.y;
        zs[i] = p.z;
    }
    __syncthreads();

    const int lane   = threadIdx.x & 31;
    const int gwarp  = (blockIdx.x * blockDim.x + threadIdx.x) >> 5;
    const int nwarps = (gridDim.x * blockDim.x) >> 5;
    const unsigned lt_mask = (1u << lane) - 1u;

    for (int q = gwarp; q < NQ; q += nwarps) {
        const float qx = pg[3 * q + 0];
        const float qy = pg[3 * q + 1];
        const float qz = pg[3 * q + 2];
        const float q2 = qx * qx + qy * qy + qz * qz;

        int cnt = 0;

        // ---- phase 1: SMEM-cached prefix, 2 chunks (64 pts) per iter ----
        for (int base = 0; base < NPC; base += 64) {
            const int iA = base + lane;
            const float pxA = xs[iA];
            const float pyA = ys[iA];
            const float pzA = zs[iA];
            const int iB = base + 32 + lane;
            const float pxB = xs[iB];
            const float pyB = ys[iB];
            const float pzB = zs[iB];

            const float psA  = pxA * pxA + pyA * pyA + pzA * pzA;
            const float dotA = qx * pxA + qy * pyA + qz * pzA;
            const float d2A  = q2 + psA - 2.0f * dotA;
            const float psB  = pxB * pxB + pyB * pyB + pzB * pzB;
            const float dotB = qx * pxB + qy * pyB + qz * pzB;
            const float d2B  = q2 + psB - 2.0f * dotB;

            const bool vA = (d2A <= R2C);
            const bool vB = (d2B <= R2C);
            const unsigned mA = __ballot_sync(0xffffffffu, vA);
            const unsigned mB = __ballot_sync(0xffffffffu, vB);

            if (vA) {
                const int slot = cnt + __popc(mA & lt_mask);
                if (slot < KNN) {
                    out[(size_t)q * KNN + slot] = (float)iA;
                    float* oc = out + MAP_ELEMS + ((size_t)q * KNN + slot) * 3;
                    oc[0] = pxA; oc[1] = pyA; oc[2] = pzA;
                }
            }
            cnt += __popc(mA);
            if (vB) {
                const int slot = cnt + __popc(mB & lt_mask);
                if (slot < KNN) {
                    out[(size_t)q * KNN + slot] = (float)iB;
                    float* oc = out + MAP_ELEMS + ((size_t)q * KNN + slot) * 3;
                    oc[0] = pxB; oc[1] = pyB; oc[2] = pzB;
                }
            }
            cnt += __popc(mB);

            if (cnt >= KNN) break;   // warp-uniform
        }

        // ---- phase 2 (rare, ~2-3% of queries): tail from global ----
        if (cnt < KNN) {
            for (int base = NPC; base < NP; base += 32) {
                const int i = base + lane;
                const float px = x[3 * i + 0];
                const float py = x[3 * i + 1];
                const float pz = x[3 * i + 2];
                const float ps  = px * px + py * py + pz * pz;
                const float dot = qx * px + qy * py + qz * pz;
                const float d2  = q2 + ps - 2.0f * dot;
                const bool valid = (d2 <= R2C);
                const unsigned mask = __ballot_sync(0xffffffffu, valid);
                if (valid) {
                    const int slot = cnt + __popc(mask & lt_mask);
                    if (slot < KNN) {
                        out[(size_t)q * KNN + slot] = (float)i;
                        float* oc = out + MAP_ELEMS + ((size_t)q * KNN + slot) * 3;
                        oc[0] = px; oc[1] = py; oc[2] = pz;
                    }
                }
                cnt += __popc(mask);
                if (cnt >= KNN) break;
            }
        }

        // ---- zero-fill unfound slots ----
        const int c = cnt < KNN ? cnt : KNN;
        if (lane >= c && lane < KNN) {
            out[(size_t)q * KNN + lane] = 0.0f;
            float* oc = out + MAP_ELEMS + ((size_t)q * KNN + lane) * 3;
            oc[0] = 0.0f; oc[1] = 0.0f; oc[2] = 0.0f;
        }
    }
}

extern "C" void kernel_launch(void* const* d_in, const int* in_sizes, int n_in,
                              void* d_out, int out_size)
{
    const float* x  = (const float*)d_in[0];   // (1, 8192, 3)
    const float* pg = (const float*)d_in[1];   // (1, 64, 32, 16, 3)
    if (n_in >= 2 && in_sizes[0] == NQ * 3 && in_sizes[1] == NP * 3) {
        const float* t = x; x = pg; pg = t;
    }
    float* out = (float*)d_out;

    const int threads = 256;
    const int blocks  = 1184;   // ~8 CTAs/SM persistent-ish; grid-stride warps

    bq_kernel<<<blocks, threads>>>(x, pg, out);
}

// round 4
// speedup vs baseline: 1.2695x; 1.0778x over previous
#include <cuda_runtime.h>
#include <cuda_bf16.h>

// Ball query: for each of NQ=32768 query points (p_grid), find first K=10
// points of x (NP=8192) with d2 <= RADIUS^2, ascending index order.
//
// Output buffer (float32), out_size = NQ*K + NQ*K*3:
//   [0 .. NQ*K)        mapping (index as float, 0 if not found)
//   [NQ*K .. NQ*K*4)   gathered coords (x[mapping], zeroed if not found)
//
// R3: float4 (x,y,z,|p|^2) SMEM cache -> 1 LDS.128/pt; hit indices deferred
// to per-warp scratch, output written once per query in an epilogue.

#define NP 8192
#define NQ 32768
#define KNN 10
#define R2C 0.0625f
#define MAP_ELEMS (NQ * KNN)
#define NPC 2048            // points cached in SMEM (32 KB as float4)
#define WARPS_PER_CTA 8

__global__ void __launch_bounds__(256)
bq_kernel(const float* __restrict__ x,
          const float* __restrict__ pg,
          float* __restrict__ out)
{
    __shared__ float4 pts[NPC];                       // 32 KB
    __shared__ int scratch[WARPS_PER_CTA][16];        // hit indices (10 used)

    for (int i = threadIdx.x; i < NPC; i += blockDim.x) {
        const float px = x[3 * i + 0];
        const float py = x[3 * i + 1];
        const float pz = x[3 * i + 2];
        const float ps = px * px + py * py + pz * pz; // same expr as before
        pts[i] = make_float4(px, py, pz, ps);
    }
    __syncthreads();

    const int lane   = threadIdx.x & 31;
    const int warp   = threadIdx.x >> 5;
    const int gwarp  = (blockIdx.x * blockDim.x + threadIdx.x) >> 5;
    const int nwarps = (gridDim.x * blockDim.x) >> 5;
    const unsigned lt_mask = (1u << lane) - 1u;

    for (int q = gwarp; q < NQ; q += nwarps) {
        const float qx = pg[3 * q + 0];
        const float qy = pg[3 * q + 1];
        const float qz = pg[3 * q + 2];
        const float q2 = qx * qx + qy * qy + qz * qz;

        int cnt = 0;

        // ---- phase 1: SMEM-cached prefix, 64 pts / iteration ----
        for (int base = 0; base < NPC; base += 64) {
            const float4 A = pts[base + lane];
            const float4 B = pts[base + 32 + lane];

            const float dotA = qx * A.x + qy * A.y + qz * A.z;
            const float d2A  = q2 + A.w - 2.0f * dotA;
            const float dotB = qx * B.x + qy * B.y + qz * B.z;
            const float d2B  = q2 + B.w - 2.0f * dotB;

            const bool vA = (d2A <= R2C);
            const bool vB = (d2B <= R2C);
            const unsigned mA = __ballot_sync(0xffffffffu, vA);
            const unsigned mB = __ballot_sync(0xffffffffu, vB);

            if (vA) {
                const int slot = cnt + __popc(mA & lt_mask);
                if (slot < KNN) scratch[warp][slot] = base + lane;
            }
            cnt += __popc(mA);
            if (vB) {
                const int slot = cnt + __popc(mB & lt_mask);
                if (slot < KNN) scratch[warp][slot] = base + 32 + lane;
            }
            cnt += __popc(mB);

            if (cnt >= KNN) break;   // warp-uniform
        }

        // ---- phase 2 (rare): tail from global, identical math ----
        if (cnt < KNN) {
            for (int base = NPC; base < NP; base += 32) {
                const int i = base + lane;
                const float px = x[3 * i + 0];
                const float py = x[3 * i + 1];
                const float pz = x[3 * i + 2];
                const float ps  = px * px + py * py + pz * pz;
                const float dot = qx * px + qy * py + qz * pz;
                const float d2  = q2 + ps - 2.0f * dot;
                const bool valid = (d2 <= R2C);
                const unsigned mask = __ballot_sync(0xffffffffu, valid);
                if (valid) {
                    const int slot = cnt + __popc(mask & lt_mask);
                    if (slot < KNN) scratch[warp][slot] = i;
                }
                cnt += __popc(mask);
                if (cnt >= KNN) break;
            }
        }

        __syncwarp();   // make scratch STS visible to all lanes

        // ---- epilogue: lanes 0..9 emit mapping + coords ----
        const int c = cnt < KNN ? cnt : KNN;
        if (lane < KNN) {
            const bool found = (lane < c);
            const int idx = found ? scratch[warp][lane] : 0;
            out[(size_t)q * KNN + lane] = found ? (float)idx : 0.0f;

            float px = 0.0f, py = 0.0f, pz = 0.0f;
            if (found) {
                if (idx < NPC) {
                    const float4 t = pts[idx];
                    px = t.x; py = t.y; pz = t.z;
                } else {
                    px = x[3 * idx + 0];
                    py = x[3 * idx + 1];
                    pz = x[3 * idx + 2];
                }
            }
            float* oc = out + MAP_ELEMS + ((size_t)q * KNN + lane) * 3;
            oc[0] = px; oc[1] = py; oc[2] = pz;
        }
        __syncwarp();   // scratch reuse safety for next query
    }
}

extern "C" void kernel_launch(void* const* d_in, const int* in_sizes, int n_in,
                              void* d_out, int out_size)
{
    const float* x  = (const float*)d_in[0];   // (1, 8192, 3)
    const float* pg = (const float*)d_in[1];   // (1, 64, 32, 16, 3)
    if (n_in >= 2 && in_sizes[0] == NQ * 3 && in_sizes[1] == NP * 3) {
        const float* t = x; x = pg; pg = t;
    }
    float* out = (float*)d_out;

    const int threads = 256;
    const int blocks  = 1184;   // grid-stride over 32768 query-warps

    bq_kernel<<<blocks, threads>>>(x, pg, out);
}